// round 17
// baseline (speedup 1.0000x reference)
#include <cuda_runtime.h>
#include <cuda_bf16.h>

// BlockAttnRes: per-token block attention over N=9 source rows of D=512.
//   score_n = dot(src_n, w) / sqrt(mean(src_n^2)+1e-6),  alpha = softmax(score),
//   h = sum_n alpha_n * src_n.
//
// R17 = R14 (best @ 101.1us: one CTA/token, register-resident rows, query
// load first, warp-0 parallel softmax, ldcs/stcs) with ONE change: the
// per-row (ss, dt) warp reductions share a single paired butterfly chain:
//   step 1 (XOR-16): lanes 0-15 accumulate ss, lanes 16-31 accumulate dt
//   steps 2-5 (XOR 8/4/2/1): both halves reduce simultaneously
// 5 SHFL per row instead of 10 -> halves the dominant SHFL workload on the
// load->barrier critical path. (redux.sync.f32 does not exist on sm_103.)

#define NN 9
#define DD 512
#define THREADS 128

__global__ __launch_bounds__(THREADS)
void blockattn_kernel(const float* __restrict__ src,
                      const float* __restrict__ queries,
                      const int*   __restrict__ layer_idx,
                      float*       __restrict__ out)
{
    const int tid  = threadIdx.x;
    const int lane = tid & 31;
    const int warp = tid >> 5;

    const long long token = blockIdx.x;
    const float4* base = reinterpret_cast<const float4*>(src + token * (long long)(NN * DD));

    // Query row (L2-resident, broadcast across all CTAs) — issued FIRST.
    const int li = *layer_idx;
    const float4 w4 = reinterpret_cast<const float4*>(queries + (long long)li * DD)[tid];

    // ---- Phase 1: load all 9 rows into registers (streaming, coalesced) ----
    float4 v[NN];
#pragma unroll
    for (int n = 0; n < NN; n++)
        v[n] = __ldcs(base + n * (DD / 4) + tid);

    // ---- Per-row partials + paired warp reduction (ss & dt in one chain) ----
    __shared__ float s_ss[NN][4];
    __shared__ float s_dt[NN][4];
    __shared__ float s_alpha[NN];

    const bool hiHalf = (lane & 16) != 0;

#pragma unroll
    for (int n = 0; n < NN; n++) {
        const float4 a = v[n];
        const float ssn = a.x * a.x + a.y * a.y + a.z * a.z + a.w * a.w;
        const float dtn = a.x * w4.x + a.y * w4.y + a.z * w4.z + a.w * w4.w;

        // Pair step: low half keeps ss (receives partner's ss),
        //            high half keeps dt (receives partner's dt).
        const float send = hiHalf ? ssn : dtn;
        const float keep = hiHalf ? dtn : ssn;
        float t = keep + __shfl_xor_sync(0xffffffffu, send, 16);

        // Joint butterfly: both halves reduce over their 16 lanes.
#pragma unroll
        for (int o = 8; o > 0; o >>= 1)
            t += __shfl_xor_sync(0xffffffffu, t, o);

        // lanes 0-15 hold sum(ss); lanes 16-31 hold sum(dt).
        if (lane == 0)  s_ss[n][warp] = t;
        if (lane == 16) s_dt[n][warp] = t;
    }
    __syncthreads();

    // ---- Softmax on warp 0: lane n owns row n (parallel MUFU) ----
    if (warp == 0) {
        float sc = -3.4e38f;
        if (lane < NN) {
            const float S  = s_ss[lane][0] + s_ss[lane][1] + s_ss[lane][2] + s_ss[lane][3];
            const float Dt = s_dt[lane][0] + s_dt[lane][1] + s_dt[lane][2] + s_dt[lane][3];
            sc = Dt * rsqrtf(S * (1.0f / DD) + 1e-6f);
        }
        float mx = sc;
#pragma unroll
        for (int o = 16; o > 0; o >>= 1)
            mx = fmaxf(mx, __shfl_xor_sync(0xffffffffu, mx, o));

        float e = (lane < NN) ? __expf(sc - mx) : 0.0f;
        float sum = e;
#pragma unroll
        for (int o = 16; o > 0; o >>= 1)
            sum += __shfl_xor_sync(0xffffffffu, sum, o);

        if (lane < NN)
            s_alpha[lane] = e / sum;
    }
    __syncthreads();

    // ---- Phase 2: weighted sum from register-resident rows ----
    float4 o = make_float4(0.f, 0.f, 0.f, 0.f);
#pragma unroll
    for (int n = 0; n < NN; n++) {
        const float a = s_alpha[n];
        o.x += a * v[n].x;
        o.y += a * v[n].y;
        o.z += a * v[n].z;
        o.w += a * v[n].w;
    }

    __stcs(reinterpret_cast<float4*>(out + token * (long long)DD) + tid, o);
}

extern "C" void kernel_launch(void* const* d_in, const int* in_sizes, int n_in,
                              void* d_out, int out_size)
{
    const float* src     = (const float*)d_in[0];
    const float* queries = (const float*)d_in[1];
    const int*   lidx    = (const int*)d_in[2];
    float*       out     = (float*)d_out;

    const int tokens = in_sizes[0] / (NN * DD);   // B*T = 32768
    blockattn_kernel<<<tokens, THREADS>>>(src, queries, lidx, out);
}